// round 9
// baseline (speedup 1.0000x reference)
#include <cuda_runtime.h>
#include <math.h>

// Problem constants
#define NQ   64          // queries
#define DD   256         // feature dim
#define NS   4096        // bank size
#define IMG  65536       // C*H*W floats per image
#define FPB  32          // features per sim block
#define SIMBLOCKS (NS / FPB)   // 128

// smem layout for sim phase (transposed, padded strides)
#define QS_STRIDE 68
#define FS_STRIDE 36
#define QS_FLOATS (DD * QS_STRIDE)   // 17408
#define FS_FLOATS (DD * FS_STRIDE)   //  9216
#define RED_SLOTS (NQ * 16)
#define SMEM_BYTES ((QS_FLOATS + FS_FLOATS) * 4 + RED_SLOTS * 8)  // 114688 B

// Gather phase: each block copies 128 KB as 8 x 16 KB double-buffered TMA chunks.
#define GBUF   16384                  // bytes per buffer
#define GCH    8                      // chunks per block
#define HALF_FLOATS (IMG / 2)         // 32768 floats per gather block

__device__ unsigned long long g_part[NQ * SIMBLOCKS];
__device__ unsigned g_ctr = 0;        // monotonic epoch counter (+128 per replay)

__device__ __forceinline__ unsigned long long packkey(float f, unsigned idx) {
    unsigned u = __float_as_uint(f);
    u = (u & 0x80000000u) ? ~u : (u | 0x80000000u);
    return ((unsigned long long)u << 32) | (0xFFFFFFFFu - idx);
}
__device__ __forceinline__ float unpackscore(unsigned long long p) {
    unsigned u = (unsigned)(p >> 32);
    unsigned bits = (u & 0x80000000u) ? (u & 0x7FFFFFFFu) : ~u;
    return __uint_as_float(bits);
}
__device__ __forceinline__ unsigned long long umax64(unsigned long long a,
                                                     unsigned long long b) {
    return a > b ? a : b;
}
__device__ __forceinline__ unsigned smem_u32(const void* p) {
    unsigned a;
    asm("{ .reg .u64 t; cvta.to.shared.u64 t, %1; cvt.u32.u64 %0, t; }"
        : "=r"(a) : "l"(p));
    return a;
}
__device__ __forceinline__ void mbar_wait(unsigned mb, unsigned parity) {
    unsigned done;
    asm volatile(
        "{\n\t.reg .pred p;\n\t"
        "mbarrier.try_wait.parity.acquire.cta.shared::cta.b64 p, [%1], %2;\n\t"
        "selp.b32 %0, 1, 0, p;\n\t}"
        : "=r"(done) : "r"(mb), "r"(parity) : "memory");
    if (!done) {
        asm volatile(
            "{\n\t.reg .pred P1;\n\t"
            "WL_%=:\n\t"
            "mbarrier.try_wait.parity.acquire.cta.shared::cta.b64 P1, [%0], %1, 0x989680;\n\t"
            "@P1 bra.uni WD_%=;\n\t"
            "bra.uni WL_%=;\n\t"
            "WD_%=:\n\t}"
            :: "r"(mb), "r"(parity) : "memory");
    }
}

// ---------------------------------------------------------------------------
// Fused kernel, grid = 128 blocks x 256 threads (1 block/SM -> all co-resident).
// Phase 1: sim tile GEMM (64 q x 32 f x K=256) on RAW q + per-block argmax.
// Device-wide epoch barrier.
// Phase 2: block b = (query b>>1, half b&1): final argmax reduce + pipelined
// TMA bulk copy of 128 KB + normalized score write (half 0, warp 1).
// ---------------------------------------------------------------------------
__global__ void __launch_bounds__(256, 1)
fused_kernel(const float* __restrict__ q, const float* __restrict__ feats,
             const float* __restrict__ images, float* __restrict__ out) {
    extern __shared__ float sm[];

    const int tid  = threadIdx.x;
    const int lane = tid & 31;
    const int warp = tid >> 5;

    // ================= Phase 1: similarity GEMM + block argmax ============
    {
        float* qs = sm;                          // [256][68]
        float* fs = sm + QS_FLOATS;              // [256][36]
        unsigned long long* red =
            (unsigned long long*)(sm + QS_FLOATS + FS_FLOATS);   // [64][16]

        const int f0 = blockIdx.x * FPB;
        const int dr = lane >> 3;                // 0..3
        const int dk = lane & 7;                 // 0..7

        #pragma unroll 4
        for (int g = warp; g < 512; g += 8) {    // stage q transposed
            int rb = g & 15, kb = g >> 4;
            int r = rb * 4 + dr, k = kb * 8 + dk;
            qs[k * QS_STRIDE + r] = q[r * DD + k];
        }
        #pragma unroll 4
        for (int g = warp; g < 256; g += 8) {    // stage feature rows transposed
            int rb = g & 7, kb = g >> 3;
            int r = rb * 4 + dr, k = kb * 8 + dk;
            fs[k * FS_STRIDE + r] = feats[(size_t)(f0 + r) * DD + k];
        }
        __syncthreads();

        const int tx = tid & 15;                 // q rows 4tx..4tx+3
        const int ty = tid >> 4;                 // f cols 2ty, 2ty+1
        float acc[4][2];
        #pragma unroll
        for (int i = 0; i < 4; i++) { acc[i][0] = 0.f; acc[i][1] = 0.f; }

        #pragma unroll 8
        for (int k = 0; k < DD; k++) {
            float4 a = *reinterpret_cast<const float4*>(&qs[k * QS_STRIDE + 4 * tx]);
            float2 b = *reinterpret_cast<const float2*>(&fs[k * FS_STRIDE + 2 * ty]);
            float av[4] = {a.x, a.y, a.z, a.w};
            #pragma unroll
            for (int i = 0; i < 4; i++) {
                acc[i][0] = fmaf(av[i], b.x, acc[i][0]);
                acc[i][1] = fmaf(av[i], b.y, acc[i][1]);
            }
        }

        #pragma unroll
        for (int i = 0; i < 4; i++) {
            float m = acc[i][0]; int bj = 0;
            if (acc[i][1] > m) { m = acc[i][1]; bj = 1; }
            red[(4 * tx + i) * 16 + ty] = packkey(m, (unsigned)(f0 + 2 * ty + bj));
        }
        __syncthreads();

        if (tid < NQ) {
            unsigned long long p = red[tid * 16];
            #pragma unroll
            for (int j = 1; j < 16; j++) p = umax64(p, red[tid * 16 + j]);
            g_part[tid * SIMBLOCKS + blockIdx.x] = p;
        }
    }
    __syncthreads();

    // ================= Device-wide epoch barrier ==========================
    // Counter is monotonic (+SIMBLOCKS per replay) -> no reset kernel needed.
    if (tid == 0) {
        __threadfence();
        unsigned old = atomicAdd(&g_ctr, 1u);
        unsigned target = ((old >> 7) + 1u) << 7;   // end of this epoch
        unsigned v;
        do {
            asm volatile("ld.acquire.gpu.u32 %0, [%1];" : "=r"(v) : "l"(&g_ctr));
        } while ((int)(v - target) < 0);
    }
    __syncthreads();

    // ================= Phase 2: reduce + pipelined gather =================
    char* smb = (char*)sm;
    // buffers at 0 and GBUF; control block after 2*GBUF
    unsigned long long* mb64  = (unsigned long long*)(smb + 2 * GBUF);  // [2] mbarriers
    unsigned long long* sred  = mb64 + 2;                                // [4]
    unsigned long long* sbest = sred + 4;                                // [1]

    const int qi = blockIdx.x >> 1;
    const int h  = blockIdx.x & 1;

    unsigned long long p = 0ull;
    if (tid < SIMBLOCKS) {
        p = g_part[qi * SIMBLOCKS + tid];
        #pragma unroll
        for (int o = 16; o; o >>= 1)
            p = umax64(p, __shfl_xor_sync(0xffffffffu, p, o));
        if ((tid & 31) == 0) sred[tid >> 5] = p;
    }
    if (tid == 0) {
        const unsigned m0 = smem_u32(&mb64[0]);
        const unsigned m1 = smem_u32(&mb64[1]);
        asm volatile("mbarrier.init.shared.b64 [%0], 1;" :: "r"(m0) : "memory");
        asm volatile("mbarrier.init.shared.b64 [%0], 1;" :: "r"(m1) : "memory");
        asm volatile("fence.proxy.async.shared::cta;" ::: "memory");
    }
    __syncthreads();

    unsigned long long best = umax64(umax64(sred[0], sred[1]),
                                     umax64(sred[2], sred[3]));
    if (tid == 0) *sbest = best;

    // t0 drives the double-buffered TMA bulk pipeline: 8 x 16 KB.
    if (tid == 0) {
        const unsigned idx = 0xFFFFFFFFu - (unsigned)(best & 0xFFFFFFFFu);
        const char* src = (const char*)(images + (size_t)idx * IMG
                                        + (size_t)h * HALF_FLOATS);
        char* dst = (char*)(out + (size_t)qi * IMG + (size_t)h * HALF_FLOATS);
        const unsigned sb[2] = { smem_u32(smb), smem_u32(smb + GBUF) };
        const unsigned mb[2] = { smem_u32(&mb64[0]), smem_u32(&mb64[1]) };

        // prime: load chunk 0 into buffer 0
        asm volatile("mbarrier.arrive.expect_tx.shared.b64 _, [%0], %1;"
                     :: "r"(mb[0]), "r"((unsigned)GBUF) : "memory");
        asm volatile(
            "cp.async.bulk.shared::cta.global.mbarrier::complete_tx::bytes "
            "[%0], [%1], %2, [%3];"
            :: "r"(sb[0]), "l"(src), "r"((unsigned)GBUF), "r"(mb[0]) : "memory");

        #pragma unroll
        for (int c = 0; c < GCH; c++) {
            const int b = c & 1;
            mbar_wait(mb[b], (unsigned)((c >> 1) & 1));
            asm volatile("fence.proxy.async.shared::cta;" ::: "memory");
            asm volatile(
                "cp.async.bulk.global.shared::cta.bulk_group [%0], [%1], %2;"
                :: "l"(dst + (size_t)c * GBUF), "r"(sb[b]), "r"((unsigned)GBUF)
                : "memory");
            asm volatile("cp.async.bulk.commit_group;" ::: "memory");
            if (c + 1 < GCH) {
                // ensure the other buffer's store (group c-1) has drained
                asm volatile("cp.async.bulk.wait_group 1;" ::: "memory");
                asm volatile("mbarrier.arrive.expect_tx.shared.b64 _, [%0], %1;"
                             :: "r"(mb[b ^ 1]), "r"((unsigned)GBUF) : "memory");
                asm volatile(
                    "cp.async.bulk.shared::cta.global.mbarrier::complete_tx::bytes "
                    "[%0], [%1], %2, [%3];"
                    :: "r"(sb[b ^ 1]), "l"(src + (size_t)(c + 1) * GBUF),
                       "r"((unsigned)GBUF), "r"(mb[b ^ 1]) : "memory");
            }
        }
        asm volatile("cp.async.bulk.wait_group 0;" ::: "memory");
    }

    // Warp 1 of half-0 blocks: ||q_qi|| and normalized score (overlaps t0's TMA).
    if (h == 0 && warp == 1) {
        const float4* qr = reinterpret_cast<const float4*>(q + qi * DD);
        float s = 0.f;
        #pragma unroll
        for (int j = 0; j < 2; j++) {
            float4 w = qr[lane + 32 * j];
            s += w.x * w.x + w.y * w.y + w.z * w.z + w.w * w.w;
        }
        #pragma unroll
        for (int o = 16; o; o >>= 1) s += __shfl_xor_sync(0xffffffffu, s, o);
        if (lane == 0) {
            float norm = fmaxf(sqrtf(s), 1e-12f);
            out[(size_t)NQ * IMG + qi] = unpackscore(best) / norm;
        }
    }
    __syncthreads();   // keep smem (buffers/mbars) alive until TMA ops done
}

// ---------------------------------------------------------------------------
extern "C" void kernel_launch(void* const* d_in, const int* in_sizes, int n_in,
                              void* d_out, int out_size) {
    const float* q      = (const float*)d_in[0];   // (64, 256)
    const float* feats  = (const float*)d_in[1];   // (4096, 256), pre-normalized
    const float* images = (const float*)d_in[2];   // (4096, 1, 256, 256)
    float* out = (float*)d_out;                    // 64*65536 imgs + 64 scores

    cudaFuncSetAttribute(fused_kernel,
                         cudaFuncAttributeMaxDynamicSharedMemorySize, SMEM_BYTES);

    fused_kernel<<<SIMBLOCKS, 256, SMEM_BYTES>>>(q, feats, images, out);
}

// round 11
// speedup vs baseline: 1.2000x; 1.2000x over previous
#include <cuda_runtime.h>
#include <math.h>

// Problem constants
#define NQ   64          // queries
#define DD   256         // feature dim
#define NS   4096        // bank size
#define IMG  65536       // C*H*W floats per image
#define FPB  32          // features per sim block
#define SIMBLOCKS (NS / FPB)   // 128

// smem layout for sim kernel (transposed, padded strides)
#define QS_STRIDE 68     // 64 rows + 4 pad (float4-aligned reads, conflict-free)
#define FS_STRIDE 36     // 32 rows + 4 pad
#define QS_FLOATS (DD * QS_STRIDE)   // 17408
#define FS_FLOATS (DD * FS_STRIDE)   //  9216
#define RED_SLOTS (NQ * 16)          // per-(query, ty) partials
#define SMEM_BYTES ((QS_FLOATS + FS_FLOATS) * 4 + RED_SLOTS * 8)  // 114688 B

// Per-(query, sim-block) partial argmax results. Every slot is rewritten on
// every replay -> no reset kernel, no atomics, fully deterministic.
__device__ unsigned long long g_part[NQ * SIMBLOCKS];

__device__ __forceinline__ unsigned long long packkey(float f, unsigned idx) {
    unsigned u = __float_as_uint(f);
    u = (u & 0x80000000u) ? ~u : (u | 0x80000000u);
    return ((unsigned long long)u << 32) | (0xFFFFFFFFu - idx);
}
__device__ __forceinline__ float unpackscore(unsigned long long p) {
    unsigned u = (unsigned)(p >> 32);
    unsigned bits = (u & 0x80000000u) ? (u & 0x7FFFFFFFu) : ~u;
    return __uint_as_float(bits);
}
__device__ __forceinline__ unsigned long long umax64(unsigned long long a,
                                                     unsigned long long b) {
    return a > b ? a : b;
}

// ---------------------------------------------------------------------------
// Kernel 1: sim tile GEMM (64 q x 32 f x K=256) on RAW q + fused argmax.
// argmax(q.F^T) == argmax(q_hat.F^T) since 1/||q|| > 0; norm applied at
// score-write time. 256 threads (8 warps), thread tile 4x2.
// Staging: coalesced LDG.128 (q: 16 float4/thread in 2 batches, feats:
// 8 float4/thread), transpose on the STS side. Full K coverage:
//   q:    thread (r=tid>>2, c=tid&3) loads groups c+4i, i in [0,16) -> 0..63
//   feat: thread (r=tid>>3, c=tid&7) loads groups c+8i, i in [0,8)  -> 0..63
// ---------------------------------------------------------------------------
__global__ void __launch_bounds__(256, 1) sim_kernel(const float* __restrict__ q,
                                                     const float* __restrict__ feats) {
    extern __shared__ float sm[];
    float* qs = sm;                          // [256][68]  qs[k*68 + qrow]
    float* fs = sm + QS_FLOATS;              // [256][36]  fs[k*36 + frow]
    unsigned long long* red =
        (unsigned long long*)(sm + QS_FLOATS + FS_FLOATS);   // [64][16]

    const int tid = threadIdx.x;
    const int f0  = blockIdx.x * FPB;

    // ---- Stage q transposed: 16 coalesced float4 loads per thread ----
    {
        const float4* q4 = reinterpret_cast<const float4*>(q);
        const int r = tid >> 2;              // 0..63 (warp spans 8 rows x 64B)
        const int c = tid & 3;
        #pragma unroll
        for (int half = 0; half < 2; half++) {
            float4 v[8];
            #pragma unroll
            for (int i = 0; i < 8; i++)
                v[i] = q4[r * 64 + c + 4 * (half * 8 + i)];
            #pragma unroll
            for (int i = 0; i < 8; i++) {
                const int k = 4 * (c + 4 * (half * 8 + i));
                qs[(k + 0) * QS_STRIDE + r] = v[i].x;
                qs[(k + 1) * QS_STRIDE + r] = v[i].y;
                qs[(k + 2) * QS_STRIDE + r] = v[i].z;
                qs[(k + 3) * QS_STRIDE + r] = v[i].w;
            }
        }
    }
    // ---- Stage feature tile transposed: 8 coalesced float4 loads per thread ----
    {
        const float4* f4 =
            reinterpret_cast<const float4*>(feats + (size_t)f0 * DD);
        const int r = tid >> 3;              // 0..31 (warp spans 4 rows x 128B)
        const int c = tid & 7;
        float4 w[8];
        #pragma unroll
        for (int i = 0; i < 8; i++)
            w[i] = f4[r * 64 + c + 8 * i];
        #pragma unroll
        for (int i = 0; i < 8; i++) {
            const int k = 4 * (c + 8 * i);
            fs[(k + 0) * FS_STRIDE + r] = w[i].x;
            fs[(k + 1) * FS_STRIDE + r] = w[i].y;
            fs[(k + 2) * FS_STRIDE + r] = w[i].z;
            fs[(k + 3) * FS_STRIDE + r] = w[i].w;
        }
    }
    __syncthreads();

    const int tx = tid & 15;                 // q rows 4tx..4tx+3
    const int ty = tid >> 4;                 // f cols 2ty, 2ty+1
    float acc[4][2];
    #pragma unroll
    for (int i = 0; i < 4; i++) { acc[i][0] = 0.f; acc[i][1] = 0.f; }

    #pragma unroll 8
    for (int k = 0; k < DD; k++) {
        float4 a = *reinterpret_cast<const float4*>(&qs[k * QS_STRIDE + 4 * tx]);
        float2 b = *reinterpret_cast<const float2*>(&fs[k * FS_STRIDE + 2 * ty]);
        float av[4] = {a.x, a.y, a.z, a.w};
        #pragma unroll
        for (int i = 0; i < 4; i++) {
            acc[i][0] = fmaf(av[i], b.x, acc[i][0]);
            acc[i][1] = fmaf(av[i], b.y, acc[i][1]);
        }
    }

    // Per-thread max over its 2 features (strict > keeps lowest index on tie)
    #pragma unroll
    for (int i = 0; i < 4; i++) {
        float m = acc[i][0]; int bj = 0;
        if (acc[i][1] > m) { m = acc[i][1]; bj = 1; }
        red[(4 * tx + i) * 16 + ty] = packkey(m, (unsigned)(f0 + 2 * ty + bj));
    }
    __syncthreads();

    // One thread per query reduces the 16 ty-partials -> its private slot.
    if (tid < NQ) {
        unsigned long long p = red[tid * 16];
        #pragma unroll
        for (int j = 1; j < 16; j++) p = umax64(p, red[tid * 16 + j]);
        g_part[tid * SIMBLOCKS + blockIdx.x] = p;
    }
}

// ---------------------------------------------------------------------------
// Kernel 2: per-query final argmax reduce (redundant per block, L2-hot 1 KB)
// + image gather (float4 streaming copy) + normalized score write.
// Grid (16 chunks, 64 queries) x 256 threads; each block copies 16 KB.
// (Best-measured gather config: R6, 9.12 us.)
// ---------------------------------------------------------------------------
__global__ void __launch_bounds__(256, 8) gather_kernel(const float* __restrict__ q,
                                                        const float* __restrict__ images,
                                                        float* __restrict__ out) {
    __shared__ unsigned long long sred[4];
    __shared__ unsigned long long sbest;

    const int qi = blockIdx.y;
    const int t  = threadIdx.x;

    // Reduce 128 per-block partials for this query.
    unsigned long long p = 0ull;
    if (t < SIMBLOCKS) p = g_part[qi * SIMBLOCKS + t];
    #pragma unroll
    for (int o = 16; o; o >>= 1)
        p = umax64(p, __shfl_xor_sync(0xffffffffu, p, o));
    if (t < SIMBLOCKS && (t & 31) == 0) sred[t >> 5] = p;
    __syncthreads();
    if (t == 0) {
        unsigned long long m = sred[0];
        #pragma unroll
        for (int j = 1; j < 4; j++) m = umax64(m, sred[j]);
        sbest = m;
    }
    __syncthreads();

    const unsigned long long best = sbest;
    const unsigned idx = 0xFFFFFFFFu - (unsigned)(best & 0xFFFFFFFFu);

    // Streaming copy of the selected image chunk (loads batched for MLP).
    const float4* src = reinterpret_cast<const float4*>(images + (size_t)idx * IMG)
                        + blockIdx.x * 1024;
    float4* dst = reinterpret_cast<float4*>(out + (size_t)qi * IMG)
                  + blockIdx.x * 1024;
    float4 v[4];
    #pragma unroll
    for (int r = 0; r < 4; r++) v[r] = src[t + 256 * r];
    #pragma unroll
    for (int r = 0; r < 4; r++) dst[t + 256 * r] = v[r];

    // Block (0, qi): compute ||q_qi|| with warp 0 and write normalized score.
    if (blockIdx.x == 0 && t < 32) {
        const float4* qr = reinterpret_cast<const float4*>(q + qi * DD);
        float s = 0.f;
        #pragma unroll
        for (int j = 0; j < 2; j++) {
            float4 w = qr[t + 32 * j];
            s += w.x * w.x + w.y * w.y + w.z * w.z + w.w * w.w;
        }
        #pragma unroll
        for (int o = 16; o; o >>= 1) s += __shfl_xor_sync(0xffffffffu, s, o);
        if (t == 0) {
            float norm = fmaxf(sqrtf(s), 1e-12f);
            out[(size_t)NQ * IMG + qi] = unpackscore(best) / norm;
        }
    }
}

// ---------------------------------------------------------------------------
extern "C" void kernel_launch(void* const* d_in, const int* in_sizes, int n_in,
                              void* d_out, int out_size) {
    const float* q      = (const float*)d_in[0];   // (64, 256)
    const float* feats  = (const float*)d_in[1];   // (4096, 256), pre-normalized
    const float* images = (const float*)d_in[2];   // (4096, 1, 256, 256)
    float* out = (float*)d_out;                    // 64*65536 imgs + 64 scores

    cudaFuncSetAttribute(sim_kernel,
                         cudaFuncAttributeMaxDynamicSharedMemorySize, SMEM_BYTES);

    sim_kernel<<<SIMBLOCKS, 256, SMEM_BYTES>>>(q, feats);
    gather_kernel<<<dim3(16, NQ), 256>>>(q, images, out);
}

// round 12
// speedup vs baseline: 1.2162x; 1.0135x over previous
#include <cuda_runtime.h>
#include <math.h>

// Problem constants
#define NQ   64          // queries
#define DD   256         // feature dim
#define NS   4096        // bank size
#define IMG  65536       // C*H*W floats per image
#define FPB  32          // features per sim block
#define SIMBLOCKS (NS / FPB)   // 128

// smem layout for sim kernel (transposed, padded strides)
#define QS_STRIDE 68     // 64 rows + 4 pad (float4-aligned reads, conflict-free)
#define FS_STRIDE 36     // 32 rows + 4 pad
#define QS_FLOATS (DD * QS_STRIDE)   // 17408
#define FS_FLOATS (DD * FS_STRIDE)   //  9216
#define RED_SLOTS (NQ * 16)          // per-(query, ty) partials
#define SMEM_BYTES ((QS_FLOATS + FS_FLOATS) * 4 + RED_SLOTS * 8)  // 114688 B

// Gather: 2 blocks per query, each streams 128 KB in 8 x 16 KB pipelined steps.
#define HALF_F4   8192               // float4 per half-image (128 KB)
#define GITER     8                  // iterations
#define ITER_F4   1024               // float4 per iteration (16 KB)

// Per-(query, sim-block) partial argmax results. Every slot is rewritten on
// every replay -> no reset kernel, no atomics, fully deterministic.
__device__ unsigned long long g_part[NQ * SIMBLOCKS];

__device__ __forceinline__ unsigned long long packkey(float f, unsigned idx) {
    unsigned u = __float_as_uint(f);
    u = (u & 0x80000000u) ? ~u : (u | 0x80000000u);
    return ((unsigned long long)u << 32) | (0xFFFFFFFFu - idx);
}
__device__ __forceinline__ float unpackscore(unsigned long long p) {
    unsigned u = (unsigned)(p >> 32);
    unsigned bits = (u & 0x80000000u) ? (u & 0x7FFFFFFFu) : ~u;
    return __uint_as_float(bits);
}
__device__ __forceinline__ unsigned long long umax64(unsigned long long a,
                                                     unsigned long long b) {
    return a > b ? a : b;
}

// ---------------------------------------------------------------------------
// Kernel 1: sim tile GEMM (64 q x 32 f x K=256) on RAW q + fused argmax.
// (Unchanged from R11 — measured good.)
// ---------------------------------------------------------------------------
__global__ void __launch_bounds__(256, 1) sim_kernel(const float* __restrict__ q,
                                                     const float* __restrict__ feats) {
    extern __shared__ float sm[];
    float* qs = sm;                          // [256][68]  qs[k*68 + qrow]
    float* fs = sm + QS_FLOATS;              // [256][36]  fs[k*36 + frow]
    unsigned long long* red =
        (unsigned long long*)(sm + QS_FLOATS + FS_FLOATS);   // [64][16]

    const int tid = threadIdx.x;
    const int f0  = blockIdx.x * FPB;

    // ---- Stage q transposed: 16 coalesced float4 loads per thread ----
    {
        const float4* q4 = reinterpret_cast<const float4*>(q);
        const int r = tid >> 2;              // 0..63 (warp spans 8 rows x 64B)
        const int c = tid & 3;
        #pragma unroll
        for (int half = 0; half < 2; half++) {
            float4 v[8];
            #pragma unroll
            for (int i = 0; i < 8; i++)
                v[i] = q4[r * 64 + c + 4 * (half * 8 + i)];
            #pragma unroll
            for (int i = 0; i < 8; i++) {
                const int k = 4 * (c + 4 * (half * 8 + i));
                qs[(k + 0) * QS_STRIDE + r] = v[i].x;
                qs[(k + 1) * QS_STRIDE + r] = v[i].y;
                qs[(k + 2) * QS_STRIDE + r] = v[i].z;
                qs[(k + 3) * QS_STRIDE + r] = v[i].w;
            }
        }
    }
    // ---- Stage feature tile transposed: 8 coalesced float4 loads per thread ----
    {
        const float4* f4 =
            reinterpret_cast<const float4*>(feats + (size_t)f0 * DD);
        const int r = tid >> 3;              // 0..31 (warp spans 4 rows x 128B)
        const int c = tid & 7;
        float4 w[8];
        #pragma unroll
        for (int i = 0; i < 8; i++)
            w[i] = f4[r * 64 + c + 8 * i];
        #pragma unroll
        for (int i = 0; i < 8; i++) {
            const int k = 4 * (c + 8 * i);
            fs[(k + 0) * FS_STRIDE + r] = w[i].x;
            fs[(k + 1) * FS_STRIDE + r] = w[i].y;
            fs[(k + 2) * FS_STRIDE + r] = w[i].z;
            fs[(k + 3) * FS_STRIDE + r] = w[i].w;
        }
    }
    __syncthreads();

    const int tx = tid & 15;                 // q rows 4tx..4tx+3
    const int ty = tid >> 4;                 // f cols 2ty, 2ty+1
    float acc[4][2];
    #pragma unroll
    for (int i = 0; i < 4; i++) { acc[i][0] = 0.f; acc[i][1] = 0.f; }

    #pragma unroll 8
    for (int k = 0; k < DD; k++) {
        float4 a = *reinterpret_cast<const float4*>(&qs[k * QS_STRIDE + 4 * tx]);
        float2 b = *reinterpret_cast<const float2*>(&fs[k * FS_STRIDE + 2 * ty]);
        float av[4] = {a.x, a.y, a.z, a.w};
        #pragma unroll
        for (int i = 0; i < 4; i++) {
            acc[i][0] = fmaf(av[i], b.x, acc[i][0]);
            acc[i][1] = fmaf(av[i], b.y, acc[i][1]);
        }
    }

    // Per-thread max over its 2 features (strict > keeps lowest index on tie)
    #pragma unroll
    for (int i = 0; i < 4; i++) {
        float m = acc[i][0]; int bj = 0;
        if (acc[i][1] > m) { m = acc[i][1]; bj = 1; }
        red[(4 * tx + i) * 16 + ty] = packkey(m, (unsigned)(f0 + 2 * ty + bj));
    }
    __syncthreads();

    // One thread per query reduces the 16 ty-partials -> its private slot.
    if (tid < NQ) {
        unsigned long long p = red[tid * 16];
        #pragma unroll
        for (int j = 1; j < 16; j++) p = umax64(p, red[tid * 16 + j]);
        g_part[tid * SIMBLOCKS + blockIdx.x] = p;
    }
}

// ---------------------------------------------------------------------------
// Kernel 2: per-query final argmax reduce + STREAMING image gather.
// Grid (2 halves, 64 queries) x 256 threads -> 128 blocks, one wave.
// Each block copies 128 KB as 8 x 16 KB iterations with a register double
// buffer: loads for iteration i+1 are issued before stores of iteration i,
// keeping ~16 cache lines per warp continuously in flight (steady-state
// streaming instead of one latency-bound burst).
// ---------------------------------------------------------------------------
__global__ void __launch_bounds__(256, 1) gather_kernel(const float* __restrict__ q,
                                                        const float* __restrict__ images,
                                                        float* __restrict__ out) {
    __shared__ unsigned long long sred[4];
    __shared__ unsigned long long sbest;

    const int qi = blockIdx.y;
    const int h  = blockIdx.x;
    const int t  = threadIdx.x;

    // Reduce 128 per-block partials for this query.
    unsigned long long p = 0ull;
    if (t < SIMBLOCKS) p = g_part[qi * SIMBLOCKS + t];
    #pragma unroll
    for (int o = 16; o; o >>= 1)
        p = umax64(p, __shfl_xor_sync(0xffffffffu, p, o));
    if (t < SIMBLOCKS && (t & 31) == 0) sred[t >> 5] = p;
    __syncthreads();
    if (t == 0) {
        unsigned long long m = sred[0];
        #pragma unroll
        for (int j = 1; j < 4; j++) m = umax64(m, sred[j]);
        sbest = m;
    }
    __syncthreads();

    const unsigned long long best = sbest;
    const unsigned idx = 0xFFFFFFFFu - (unsigned)(best & 0xFFFFFFFFu);

    const float4* src = reinterpret_cast<const float4*>(images + (size_t)idx * IMG)
                        + (size_t)h * HALF_F4;
    float4* dst = reinterpret_cast<float4*>(out + (size_t)qi * IMG)
                  + (size_t)h * HALF_F4;

    // Software-pipelined streaming copy: double register buffer.
    float4 cur[4], nxt[4];
    #pragma unroll
    for (int r = 0; r < 4; r++) cur[r] = __ldcs(&src[t + 256 * r]);

    #pragma unroll
    for (int it = 0; it < GITER; it++) {
        if (it + 1 < GITER) {
            const float4* s2 = src + (size_t)(it + 1) * ITER_F4;
            #pragma unroll
            for (int r = 0; r < 4; r++) nxt[r] = __ldcs(&s2[t + 256 * r]);
        }
        float4* d2 = dst + (size_t)it * ITER_F4;
        #pragma unroll
        for (int r = 0; r < 4; r++) __stcs(&d2[t + 256 * r], cur[r]);
        #pragma unroll
        for (int r = 0; r < 4; r++) cur[r] = nxt[r];
    }

    // Half-0 blocks: compute ||q_qi|| with warp 1 and write normalized score
    // (independent of the copy; overlaps with it in other warps).
    if (h == 0 && t >= 32 && t < 64) {
        const int l = t - 32;
        const float4* qr = reinterpret_cast<const float4*>(q + qi * DD);
        float s = 0.f;
        #pragma unroll
        for (int j = 0; j < 2; j++) {
            float4 w = qr[l + 32 * j];
            s += w.x * w.x + w.y * w.y + w.z * w.z + w.w * w.w;
        }
        #pragma unroll
        for (int o = 16; o; o >>= 1) s += __shfl_xor_sync(0xffffffffu, s, o);
        if (l == 0) {
            float norm = fmaxf(sqrtf(s), 1e-12f);
            out[(size_t)NQ * IMG + qi] = unpackscore(best) / norm;
        }
    }
}

// ---------------------------------------------------------------------------
extern "C" void kernel_launch(void* const* d_in, const int* in_sizes, int n_in,
                              void* d_out, int out_size) {
    const float* q      = (const float*)d_in[0];   // (64, 256)
    const float* feats  = (const float*)d_in[1];   // (4096, 256), pre-normalized
    const float* images = (const float*)d_in[2];   // (4096, 1, 256, 256)
    float* out = (float*)d_out;                    // 64*65536 imgs + 64 scores

    cudaFuncSetAttribute(sim_kernel,
                         cudaFuncAttributeMaxDynamicSharedMemorySize, SMEM_BYTES);

    sim_kernel<<<SIMBLOCKS, 256, SMEM_BYTES>>>(q, feats);
    gather_kernel<<<dim3(2, NQ), 256>>>(q, images, out);
}